// round 16
// baseline (speedup 1.0000x reference)
#include <cuda_runtime.h>
#include <math.h>

// ---------------------------------------------------------------------------
// B=2, S=2048, D=768, H=12, dk=64, FF=3072
// ---------------------------------------------------------------------------
#define B_SZ     2
#define S_LEN    2048
#define D_MODEL  768
#define N_HEADS  12
#define D_K      64
#define D_FF     3072
#define M_ROWS   (B_SZ * S_LEN)           // 4096

#define SZ_DM   (M_ROWS * D_MODEL)
#define SZ_FF   (M_ROWS * D_FF)
__device__ float g_scratch[7 * SZ_DM + SZ_FF];

#define OFF_Q    (0 * SZ_DM)
#define OFF_K    (1 * SZ_DM)
#define OFF_V    (2 * SZ_DM)
#define OFF_CTX  (3 * SZ_DM)
#define OFF_P0   (4 * SZ_DM)              // split-K partial 0
#define OFF_X1   (5 * SZ_DM)
#define OFF_P1   (6 * SZ_DM)              // split-K partial 1
#define OFF_FF   (7 * SZ_DM)

// ---------------------------------------------------------------------------
// helpers: raw fp32 bits fed to mma.tf32 (HW truncates to tf32 — no cvt)
// ---------------------------------------------------------------------------
__device__ __forceinline__ unsigned smem_u32(const void* p) {
    return (unsigned)__cvta_generic_to_shared(p);
}
#define CP16(dst_u32, src_ptr) \
    asm volatile("cp.async.cg.shared.global [%0], [%1], 16;\n" :: "r"(dst_u32), "l"(src_ptr))
#define CP_COMMIT() asm volatile("cp.async.commit_group;\n")
#define CP_WAIT0()  asm volatile("cp.async.wait_group 0;\n")

__device__ __forceinline__ void mma8(float c[4], const unsigned a[4], const unsigned b[2]) {
    asm volatile(
        "mma.sync.aligned.m16n8k8.row.col.f32.tf32.tf32.f32 "
        "{%0,%1,%2,%3}, {%4,%5,%6,%7}, {%8,%9}, {%0,%1,%2,%3};\n"
        : "+f"(c[0]), "+f"(c[1]), "+f"(c[2]), "+f"(c[3])
        : "r"(a[0]), "r"(a[1]), "r"(a[2]), "r"(a[3]), "r"(b[0]), "r"(b[1]));
}
__device__ __forceinline__ float gelu_exact(float x) {
    return 0.5f * x * (1.0f + erff(x * 0.70710678118654752440f));
}

// ---------------------------------------------------------------------------
// GEMM: C[M,N] = A[M,K] @ W[K,N] (+epilogue per MODE)
//   MODE 0: +bias   MODE 1: +bias,gelu   MODE 2: +bias,residual
//   MODE 3: raw partial (no bias) — for split-K
// Block tile 128x128, BK=32, 256 threads (8 warps, 4m x 2n), warp tile 32x64.
// cp.async double-buffered DYNAMIC smem; one barrier per 32-K tile.
// __launch_bounds__(256, 3): cap regs at 85 so 3 blocks/SM are resident
// (R15 ncu showed regs=96 -> occ 2 blocks, issue 26% = latency-bound).
// ---------------------------------------------------------------------------
#define GEMM_SMEM_FLOATS (2 * 128 * 36 + 2 * 32 * 136)
#define GEMM_SMEM_BYTES  (GEMM_SMEM_FLOATS * 4)

template <int MODE>
__device__ __forceinline__ void gemm_body(
        const float* __restrict__ A, const float* __restrict__ W,
        const float* __restrict__ bias, const float* __restrict__ Res,
        float* __restrict__ C, int M, int N, int K, int lda, int bxi, int byi) {
    extern __shared__ __align__(16) float smem_dyn[];
    float* As = smem_dyn;                      // [2][128][36]
    float* Bs = smem_dyn + 2 * 128 * 36;       // [2][32][136]
#define AS(s, r, c) As[((s) * 128 + (r)) * 36 + (c)]
#define BS(s, r, c) Bs[((s) * 32 + (r)) * 136 + (c)]

    const int tid  = threadIdx.x;
    const int wid  = tid >> 5;
    const int lane = tid & 31;
    const int g    = lane >> 2;
    const int t4   = lane & 3;
    const int wm   = wid & 3;
    const int wn   = wid >> 2;
    const int bm   = byi * 128;
    const int bn   = bxi * 128;

    float c[2][8][4];
#pragma unroll
    for (int mt = 0; mt < 2; mt++)
#pragma unroll
        for (int nt = 0; nt < 8; nt++)
#pragma unroll
            for (int i = 0; i < 4; i++) c[mt][nt][i] = 0.0f;

    const int ar = tid >> 3, aq = tid & 7;     // A coords (row step 32)
    const int br = tid >> 5, bq = tid & 31;    // B coords (row step 8)

#define LOAD_TILE(stage, kbase)                                                  \
    do {                                                                         \
        _Pragma("unroll")                                                        \
        for (int i = 0; i < 4; i++) {                                            \
            int r = ar + i * 32;                                                 \
            CP16(smem_u32(&AS(stage, r, aq * 4)),                                \
                 A + (size_t)(bm + r) * lda + (kbase) + aq * 4);                 \
        }                                                                        \
        _Pragma("unroll")                                                        \
        for (int i = 0; i < 4; i++) {                                            \
            int r = br + i * 8;                                                  \
            CP16(smem_u32(&BS(stage, r, bq * 4)),                                \
                 W + (size_t)((kbase) + r) * N + bn + bq * 4);                   \
        }                                                                        \
        CP_COMMIT();                                                             \
    } while (0)

    LOAD_TILE(0, 0);
    CP_WAIT0();
    __syncthreads();

    int buf = 0;
    for (int k0 = 0; k0 < K; k0 += 32) {
        const bool has_next = (k0 + 32) < K;
        if (has_next) LOAD_TILE(buf ^ 1, k0 + 32);

#pragma unroll
        for (int kb = 0; kb < 4; kb++) {
            const int kk = kb * 8;
            unsigned a[2][4], b[8][2];
#pragma unroll
            for (int mt = 0; mt < 2; mt++) {
                int r = wm * 32 + mt * 16 + g;
                a[mt][0] = __float_as_uint(AS(buf, r,     kk + t4));
                a[mt][1] = __float_as_uint(AS(buf, r + 8, kk + t4));
                a[mt][2] = __float_as_uint(AS(buf, r,     kk + t4 + 4));
                a[mt][3] = __float_as_uint(AS(buf, r + 8, kk + t4 + 4));
            }
#pragma unroll
            for (int nt = 0; nt < 8; nt++) {
                int cb = wn * 64 + nt * 8;
                b[nt][0] = __float_as_uint(BS(buf, kk + t4,     cb + g));
                b[nt][1] = __float_as_uint(BS(buf, kk + t4 + 4, cb + g));
            }
#pragma unroll
            for (int mt = 0; mt < 2; mt++)
#pragma unroll
                for (int nt = 0; nt < 8; nt++)
                    mma8(c[mt][nt], a[mt], b[nt]);
        }

        if (has_next) CP_WAIT0();
        __syncthreads();
        buf ^= 1;
    }

    // epilogue
#pragma unroll
    for (int mt = 0; mt < 2; mt++) {
        int r0 = bm + wm * 32 + mt * 16 + g;
        int r1 = r0 + 8;
#pragma unroll
        for (int nt = 0; nt < 8; nt++) {
            int col = bn + wn * 64 + nt * 8 + t4 * 2;
            float v00 = c[mt][nt][0];
            float v01 = c[mt][nt][1];
            float v10 = c[mt][nt][2];
            float v11 = c[mt][nt][3];
            if (MODE != 3) {
                float bb0 = bias[col], bb1 = bias[col + 1];
                v00 += bb0; v01 += bb1; v10 += bb0; v11 += bb1;
            }
            if (MODE == 1) {
                v00 = gelu_exact(v00); v01 = gelu_exact(v01);
                v10 = gelu_exact(v10); v11 = gelu_exact(v11);
            }
            if (MODE == 2) {
                float2 r0v = *(const float2*)(Res + (size_t)r0 * N + col);
                float2 r1v = *(const float2*)(Res + (size_t)r1 * N + col);
                v00 += r0v.x; v01 += r0v.y; v10 += r1v.x; v11 += r1v.y;
            }
            float2 o0 = {v00, v01}, o1 = {v10, v11};
            *(float2*)(C + (size_t)r0 * N + col) = o0;
            *(float2*)(C + (size_t)r1 * N + col) = o1;
        }
    }
#undef AS
#undef BS
#undef LOAD_TILE
}

template <int MODE>
__global__ void __launch_bounds__(256, 3)
gemm_tc(const float* __restrict__ A, const float* __restrict__ W,
        const float* __restrict__ bias, const float* __restrict__ Res,
        float* __restrict__ C, int M, int N, int K) {
    gemm_body<MODE>(A, W, bias, Res, C, M, N, K, K, blockIdx.x, blockIdx.y);
}

// Split-K=2 partial GEMM: grid.z selects K-half and output partial buffer.
__global__ void __launch_bounds__(256, 3)
gemm_part(const float* __restrict__ A, const float* __restrict__ W,
          float* __restrict__ C0, float* __restrict__ C1,
          int M, int N, int Kfull) {
    const int z  = blockIdx.z;
    const int kh = Kfull >> 1;
    const float* Az = A + (size_t)z * kh;          // column offset into A
    const float* Wz = W + (size_t)z * kh * N;      // row offset into W
    float* C = z ? C1 : C0;
    gemm_body<3>(Az, Wz, nullptr, nullptr, C, M, N, kh, Kfull,
                 blockIdx.x, blockIdx.y);
}

// Fused QKV: grid.x = 18 (6 col-blocks per projection).
__global__ void __launch_bounds__(256, 3)
gemm_qkv(const float* __restrict__ A,
         const float* __restrict__ Wq, const float* __restrict__ Wk, const float* __restrict__ Wv,
         const float* __restrict__ bq, const float* __restrict__ bk, const float* __restrict__ bv,
         float* __restrict__ Oq, float* __restrict__ Ok, float* __restrict__ Ov,
         int M, int K) {
    int sel = blockIdx.x / 6;
    int bx  = blockIdx.x - sel * 6;
    const float* W    = (sel == 0) ? Wq : (sel == 1) ? Wk : Wv;
    const float* bias = (sel == 0) ? bq : (sel == 1) ? bk : bv;
    float*       C    = (sel == 0) ? Oq : (sel == 1) ? Ok : Ov;
    gemm_body<0>(A, W, bias, nullptr, C, M, D_MODEL, K, K, bx, blockIdx.y);
}

// ---------------------------------------------------------------------------
// Flash attention (R10): BQ=128, BKV=64, double-buffered cp.async pipeline.
// ---------------------------------------------------------------------------
#define BQ  128
#define BKV 64

__global__ void __launch_bounds__(256, 3)
attn_tc3(const float* __restrict__ Q, const float* __restrict__ K,
         const float* __restrict__ V, const int* __restrict__ mask,
         float* __restrict__ O) {
    __shared__ __align__(16) float Ks[2][64][68];
    __shared__ __align__(16) float Vs[2][64][68];
    __shared__ __align__(16) int   Ms[2][64];

    const int bh   = blockIdx.y;
    const int b    = bh / N_HEADS;
    const int h    = bh % N_HEADS;
    const int q0   = blockIdx.x * BQ;
    const int tid  = threadIdx.x;
    const int wid  = tid >> 5;
    const int lane = tid & 31;
    const int g    = lane >> 2;
    const int t4   = lane & 3;

    const float* Qb = Q + (size_t)b * S_LEN * D_MODEL + h * D_K;
    const float* Kb = K + (size_t)b * S_LEN * D_MODEL + h * D_K;
    const float* Vb = V + (size_t)b * S_LEN * D_MODEL + h * D_K;
    const int*   mb = mask + b * S_LEN;

    // ---- stage Q (128 x 64) through Ks[0]/Vs[0], then into registers ----
#pragma unroll
    for (int i = 0; i < 8; i++) {
        int f = tid + i * 256;
        int r = f >> 4, dq = f & 15;
        float4 v = *(const float4*)(Qb + (size_t)(q0 + r) * D_MODEL + dq * 4);
        if (r < 64) *(float4*)&Ks[0][r][dq * 4]      = v;
        else        *(float4*)&Vs[0][r - 64][dq * 4] = v;
    }
    __syncthreads();

    unsigned qf[8][4];
    {
        int r0 = wid * 16 + g;
        int r1 = r0 + 8;
        const float* row0 = (r0 < 64) ? &Ks[0][r0][0] : &Vs[0][r0 - 64][0];
        const float* row1 = (r1 < 64) ? &Ks[0][r1][0] : &Vs[0][r1 - 64][0];
#pragma unroll
        for (int kb = 0; kb < 8; kb++) {
            qf[kb][0] = __float_as_uint(row0[kb * 8 + t4]);
            qf[kb][1] = __float_as_uint(row1[kb * 8 + t4]);
            qf[kb][2] = __float_as_uint(row0[kb * 8 + t4 + 4]);
            qf[kb][3] = __float_as_uint(row1[kb * 8 + t4 + 4]);
        }
    }
    __syncthreads();   // all qf read before tile 0 overwrites Ks[0]/Vs[0]

    // full tile copy: 1024 16B-chunks each for K and V -> 4+4 CP16 per thread
#define LOAD_KV(stage, kbase)                                                    \
    do {                                                                         \
        _Pragma("unroll")                                                        \
        for (int i = 0; i < 4; i++) {                                            \
            int f = tid + i * 256;                                               \
            int r = f >> 4, dq = f & 15;                                         \
            CP16(smem_u32(&Ks[stage][r][dq * 4]),                                \
                 Kb + (size_t)((kbase) + r) * D_MODEL + dq * 4);                 \
            CP16(smem_u32(&Vs[stage][r][dq * 4]),                                \
                 Vb + (size_t)((kbase) + r) * D_MODEL + dq * 4);                 \
        }                                                                        \
        if (tid < 16)                                                            \
            CP16(smem_u32(&Ms[stage][tid * 4]), mb + (kbase) + tid * 4);         \
        CP_COMMIT();                                                             \
    } while (0)

    float o[8][4];
#pragma unroll
    for (int nt = 0; nt < 8; nt++)
#pragma unroll
        for (int i = 0; i < 4; i++) o[nt][i] = 0.0f;
    float m0 = -1e30f, m1 = -1e30f, l0 = 0.0f, l1 = 0.0f;

    const int  srcA = (lane & 28) | (t4 >> 1);
    const int  srcB = srcA + 2;
    const bool odd  = (t4 & 1) != 0;

    LOAD_KV(0, 0);

    int buf = 0;
    for (int k0 = 0; k0 < S_LEN; k0 += BKV) {
        CP_WAIT0();          // tile k0 resident
        __syncthreads();     // visible to all; prior compute done with buf^1
        if (k0 + BKV < S_LEN) LOAD_KV(buf ^ 1, k0 + BKV);

        // S = Q @ K^T  (16 q-rows x 64 kv per warp)
        float s[8][4];
#pragma unroll
        for (int nb = 0; nb < 8; nb++) {
            s[nb][0] = 0.0f; s[nb][1] = 0.0f; s[nb][2] = 0.0f; s[nb][3] = 0.0f;
        }
#pragma unroll
        for (int kb = 0; kb < 8; kb++) {
#pragma unroll
            for (int nb = 0; nb < 8; nb++) {
                unsigned bfr[2] = {
                    __float_as_uint(Ks[buf][nb * 8 + g][kb * 8 + t4]),
                    __float_as_uint(Ks[buf][nb * 8 + g][kb * 8 + t4 + 4]) };
                mma8(s[nb], qf[kb], bfr);
            }
        }

        // mask + scale + row max
        float mx0 = -1e30f, mx1 = -1e30f;
#pragma unroll
        for (int nb = 0; nb < 8; nb++) {
            int2 mm = *(const int2*)&Ms[buf][nb * 8 + 2 * t4];
            float bx = mm.x ? 0.0f : -1e9f;
            float by = mm.y ? 0.0f : -1e9f;
            s[nb][0] = s[nb][0] * 0.125f + bx;
            s[nb][1] = s[nb][1] * 0.125f + by;
            s[nb][2] = s[nb][2] * 0.125f + bx;
            s[nb][3] = s[nb][3] * 0.125f + by;
            mx0 = fmaxf(mx0, fmaxf(s[nb][0], s[nb][1]));
            mx1 = fmaxf(mx1, fmaxf(s[nb][2], s[nb][3]));
        }
        mx0 = fmaxf(mx0, __shfl_xor_sync(0xffffffffu, mx0, 1));
        mx0 = fmaxf(mx0, __shfl_xor_sync(0xffffffffu, mx0, 2));
        mx1 = fmaxf(mx1, __shfl_xor_sync(0xffffffffu, mx1, 1));
        mx1 = fmaxf(mx1, __shfl_xor_sync(0xffffffffu, mx1, 2));

        float mn0 = fmaxf(m0, mx0), mn1 = fmaxf(m1, mx1);
        float a0 = __expf(m0 - mn0), a1 = __expf(m1 - mn1);
        m0 = mn0; m1 = mn1;

        float ps0 = 0.0f, ps1 = 0.0f;
#pragma unroll
        for (int nb = 0; nb < 8; nb++) {
            float p0 = __expf(s[nb][0] - mn0); ps0 += p0;
            float p1 = __expf(s[nb][1] - mn0); ps0 += p1;
            float p2 = __expf(s[nb][2] - mn1); ps1 += p2;
            float p3 = __expf(s[nb][3] - mn1); ps1 += p3;
            s[nb][0] = p0; s[nb][1] = p1; s[nb][2] = p2; s[nb][3] = p3;
        }
        ps0 += __shfl_xor_sync(0xffffffffu, ps0, 1);
        ps0 += __shfl_xor_sync(0xffffffffu, ps0, 2);
        ps1 += __shfl_xor_sync(0xffffffffu, ps1, 1);
        ps1 += __shfl_xor_sync(0xffffffffu, ps1, 2);
        l0 = l0 * a0 + ps0;
        l1 = l1 * a1 + ps1;

        // rescale O
#pragma unroll
        for (int nt = 0; nt < 8; nt++) {
            o[nt][0] *= a0; o[nt][1] *= a0;
            o[nt][2] *= a1; o[nt][3] *= a1;
        }

        // O += P @ V   (P fragments via warp shuffles from score fragments)
#pragma unroll
        for (int kb2 = 0; kb2 < 8; kb2++) {
            unsigned c0 = __float_as_uint(s[kb2][0]);
            unsigned c1 = __float_as_uint(s[kb2][1]);
            unsigned c2 = __float_as_uint(s[kb2][2]);
            unsigned c3 = __float_as_uint(s[kb2][3]);
            unsigned e0 = __shfl_sync(0xffffffffu, c0, srcA);
            unsigned e1 = __shfl_sync(0xffffffffu, c1, srcA);
            unsigned e2 = __shfl_sync(0xffffffffu, c2, srcA);
            unsigned e3 = __shfl_sync(0xffffffffu, c3, srcA);
            unsigned f0 = __shfl_sync(0xffffffffu, c0, srcB);
            unsigned f1 = __shfl_sync(0xffffffffu, c1, srcB);
            unsigned f2 = __shfl_sync(0xffffffffu, c2, srcB);
            unsigned f3 = __shfl_sync(0xffffffffu, c3, srcB);
            unsigned af[4];
            af[0] = odd ? e1 : e0;
            af[1] = odd ? e3 : e2;
            af[2] = odd ? f1 : f0;
            af[3] = odd ? f3 : f2;
#pragma unroll
            for (int nt = 0; nt < 8; nt++) {
                unsigned bfr[2] = {
                    __float_as_uint(Vs[buf][kb2 * 8 + t4][nt * 8 + g]),
                    __float_as_uint(Vs[buf][kb2 * 8 + t4 + 4][nt * 8 + g]) };
                mma8(o[nt], af, bfr);
            }
        }
        buf ^= 1;
    }

    // finalize
    float il0 = 1.0f / l0, il1 = 1.0f / l1;
    int r0 = q0 + wid * 16 + g;
    size_t g0 = (size_t)(b * S_LEN + r0) * D_MODEL + h * D_K;
    size_t g1 = (size_t)(b * S_LEN + r0 + 8) * D_MODEL + h * D_K;
#pragma unroll
    for (int nt = 0; nt < 8; nt++) {
        float2 o0 = {o[nt][0] * il0, o[nt][1] * il0};
        float2 o1 = {o[nt][2] * il1, o[nt][3] * il1};
        *(float2*)(O + g0 + nt * 8 + 2 * t4) = o0;
        *(float2*)(O + g1 + nt * 8 + 2 * t4) = o1;
    }
#undef LOAD_KV
}

// ---------------------------------------------------------------------------
// Fused split-K reduce + residual + bias + LayerNorm.
// out = LN(res + p0 + p1 + bias). One block per row, 192 threads x float4.
// ---------------------------------------------------------------------------
__global__ void __launch_bounds__(192)
ln_fuse_kernel(const float* __restrict__ p0, const float* __restrict__ p1,
               const float* __restrict__ bias, const float* __restrict__ res,
               const float* __restrict__ gamma, const float* __restrict__ beta,
               float* __restrict__ out) {
    const int row = blockIdx.x;
    const int tid = threadIdx.x;
    const size_t base = (size_t)row * D_MODEL + tid * 4;

    float4 a  = *(const float4*)(p0 + base);
    float4 bpp = *(const float4*)(p1 + base);
    float4 rr = *(const float4*)(res + base);
    float4 bb = *(const float4*)(bias + tid * 4);
    float4 v;
    v.x = a.x + bpp.x + rr.x + bb.x;
    v.y = a.y + bpp.y + rr.y + bb.y;
    v.z = a.z + bpp.z + rr.z + bb.z;
    v.w = a.w + bpp.w + rr.w + bb.w;

    float s  = v.x + v.y + v.z + v.w;
    float sq = v.x * v.x + v.y * v.y + v.z * v.z + v.w * v.w;
#pragma unroll
    for (int off = 16; off > 0; off >>= 1) {
        s  += __shfl_xor_sync(0xffffffffu, s,  off);
        sq += __shfl_xor_sync(0xffffffffu, sq, off);
    }
    __shared__ float ss[6], ssq[6];
    int wid = tid >> 5, lane = tid & 31;
    if (lane == 0) { ss[wid] = s; ssq[wid] = sq; }
    __syncthreads();
    s = 0.0f; sq = 0.0f;
#pragma unroll
    for (int w = 0; w < 6; w++) { s += ss[w]; sq += ssq[w]; }

    const float inv_n = 1.0f / (float)D_MODEL;
    float mean = s * inv_n;
    float var  = sq * inv_n - mean * mean;
    float rstd = rsqrtf(var + 1e-5f);

    float4 gm = *(const float4*)(gamma + tid * 4);
    float4 bt = *(const float4*)(beta + tid * 4);
    float4 o;
    o.x = (v.x - mean) * rstd * gm.x + bt.x;
    o.y = (v.y - mean) * rstd * gm.y + bt.y;
    o.z = (v.z - mean) * rstd * gm.z + bt.z;
    o.w = (v.w - mean) * rstd * gm.w + bt.w;
    *(float4*)(out + base) = o;
}

// ---------------------------------------------------------------------------
// Launch
// ---------------------------------------------------------------------------
extern "C" void kernel_launch(void* const* d_in, const int* in_sizes, int n_in,
                              void* d_out, int out_size) {
    const float* x    = (const float*)d_in[0];
    const int*   mask = (const int*)  d_in[1];
    const float* wq = (const float*)d_in[2];
    const float* bq = (const float*)d_in[3];
    const float* wk = (const float*)d_in[4];
    const float* bk = (const float*)d_in[5];
    const float* wv = (const float*)d_in[6];
    const float* bv = (const float*)d_in[7];
    const float* wo = (const float*)d_in[8];
    const float* bo = (const float*)d_in[9];
    const float* w1 = (const float*)d_in[10];
    const float* b1 = (const float*)d_in[11];
    const float* w2 = (const float*)d_in[12];
    const float* b2 = (const float*)d_in[13];
    const float* g1 = (const float*)d_in[14];
    const float* be1= (const float*)d_in[15];
    const float* g2 = (const float*)d_in[16];
    const float* be2= (const float*)d_in[17];
    float* out = (float*)d_out;

    void* sptr = nullptr;
    cudaGetSymbolAddress(&sptr, g_scratch);
    float* S = (float*)sptr;
    float* q_b = S + OFF_Q;
    float* k_b = S + OFF_K;
    float* v_b = S + OFF_V;
    float* ctx = S + OFF_CTX;
    float* p0  = S + OFF_P0;
    float* x1  = S + OFF_X1;
    float* p1  = S + OFF_P1;
    float* ff  = S + OFF_FF;

    cudaFuncSetAttribute(gemm_qkv,   cudaFuncAttributeMaxDynamicSharedMemorySize, GEMM_SMEM_BYTES);
    cudaFuncSetAttribute(gemm_part,  cudaFuncAttributeMaxDynamicSharedMemorySize, GEMM_SMEM_BYTES);
    cudaFuncSetAttribute(gemm_tc<1>, cudaFuncAttributeMaxDynamicSharedMemorySize, GEMM_SMEM_BYTES);

    dim3 blk(256);
    dim3 grid_qkv(18, M_ROWS / 128);                  // 576 blocks
    dim3 grid_dm2(D_MODEL / 128, M_ROWS / 128, 2);    // 384 blocks (split-K)
    dim3 grid_ff(D_FF / 128,   M_ROWS / 128);         // 768 blocks

    gemm_qkv<<<grid_qkv, blk, GEMM_SMEM_BYTES>>>(x, wq, wk, wv, bq, bk, bv,
                                                 q_b, k_b, v_b, M_ROWS, D_MODEL);

    dim3 agrid(S_LEN / BQ, B_SZ * N_HEADS);           // 384 blocks
    attn_tc3<<<agrid, blk>>>(q_b, k_b, v_b, mask, ctx);

    // wo-projection, split-K=2 -> partials; LN1 fuses reduce+bias+residual
    gemm_part<<<grid_dm2, blk, GEMM_SMEM_BYTES>>>(ctx, wo, p0, p1,
                                                  M_ROWS, D_MODEL, D_MODEL);
    ln_fuse_kernel<<<M_ROWS, 192>>>(p0, p1, bo, x, g1, be1, x1);

    // FFN1 (gelu epilogue)
    gemm_tc<1><<<grid_ff, blk, GEMM_SMEM_BYTES>>>(x1, w1, b1, nullptr, ff,
                                                  M_ROWS, D_FF, D_MODEL);

    // FFN2, split-K=2 -> partials; LN2 fuses reduce+bias+residual
    gemm_part<<<grid_dm2, blk, GEMM_SMEM_BYTES>>>(ff, w2, p0, p1,
                                                  M_ROWS, D_MODEL, D_FF);
    ln_fuse_kernel<<<M_ROWS, 192>>>(p0, p1, b2, x1, g2, be2, out);
}

// round 17
// speedup vs baseline: 1.1000x; 1.1000x over previous
#include <cuda_runtime.h>
#include <math.h>

// ---------------------------------------------------------------------------
// B=2, S=2048, D=768, H=12, dk=64, FF=3072
// ---------------------------------------------------------------------------
#define B_SZ     2
#define S_LEN    2048
#define D_MODEL  768
#define N_HEADS  12
#define D_K      64
#define D_FF     3072
#define M_ROWS   (B_SZ * S_LEN)           // 4096

#define SZ_DM   (M_ROWS * D_MODEL)
#define SZ_FF   (M_ROWS * D_FF)
__device__ float g_scratch[7 * SZ_DM + SZ_FF];

#define OFF_Q    (0 * SZ_DM)              // q; later split-K partial 2
#define OFF_K    (1 * SZ_DM)
#define OFF_V    (2 * SZ_DM)
#define OFF_CTX  (3 * SZ_DM)
#define OFF_P0   (4 * SZ_DM)              // split-K partial 0
#define OFF_X1   (5 * SZ_DM)
#define OFF_P1   (6 * SZ_DM)              // split-K partial 1
#define OFF_FF   (7 * SZ_DM)

// ---------------------------------------------------------------------------
// helpers: raw fp32 bits fed to mma.tf32 (HW truncates to tf32 — no cvt)
// ---------------------------------------------------------------------------
__device__ __forceinline__ unsigned smem_u32(const void* p) {
    return (unsigned)__cvta_generic_to_shared(p);
}
#define CP16(dst_u32, src_ptr) \
    asm volatile("cp.async.cg.shared.global [%0], [%1], 16;\n" :: "r"(dst_u32), "l"(src_ptr))
#define CP_COMMIT() asm volatile("cp.async.commit_group;\n")
#define CP_WAIT0()  asm volatile("cp.async.wait_group 0;\n")

__device__ __forceinline__ void mma8(float c[4], const unsigned a[4], const unsigned b[2]) {
    asm volatile(
        "mma.sync.aligned.m16n8k8.row.col.f32.tf32.tf32.f32 "
        "{%0,%1,%2,%3}, {%4,%5,%6,%7}, {%8,%9}, {%0,%1,%2,%3};\n"
        : "+f"(c[0]), "+f"(c[1]), "+f"(c[2]), "+f"(c[3])
        : "r"(a[0]), "r"(a[1]), "r"(a[2]), "r"(a[3]), "r"(b[0]), "r"(b[1]));
}
__device__ __forceinline__ float gelu_exact(float x) {
    return 0.5f * x * (1.0f + erff(x * 0.70710678118654752440f));
}

// ---------------------------------------------------------------------------
// GEMM: C[M,N] = A[M,K] @ W[K,N] (+epilogue per MODE)
//   MODE 0: +bias   MODE 1: +bias,gelu   MODE 2: +bias,residual
//   MODE 3: raw partial (no bias) — for split-K
// Block tile 128x128, BK=32, 256 threads (8 warps, 4m x 2n), warp tile 32x64.
// cp.async double-buffered DYNAMIC smem; one barrier per 32-K tile.
// No minBlocksPerMultiprocessor hint: natural 96 regs / occ 2 beats spilling
// (R16 measured: forcing occ 3 via reg cap regressed 750 -> 809 us).
// ---------------------------------------------------------------------------
#define GEMM_SMEM_FLOATS (2 * 128 * 36 + 2 * 32 * 136)
#define GEMM_SMEM_BYTES  (GEMM_SMEM_FLOATS * 4)

template <int MODE>
__device__ __forceinline__ void gemm_body(
        const float* __restrict__ A, const float* __restrict__ W,
        const float* __restrict__ bias, const float* __restrict__ Res,
        float* __restrict__ C, int M, int N, int K, int lda, int bxi, int byi) {
    extern __shared__ __align__(16) float smem_dyn[];
    float* As = smem_dyn;                      // [2][128][36]
    float* Bs = smem_dyn + 2 * 128 * 36;       // [2][32][136]
#define AS(s, r, c) As[((s) * 128 + (r)) * 36 + (c)]
#define BS(s, r, c) Bs[((s) * 32 + (r)) * 136 + (c)]

    const int tid  = threadIdx.x;
    const int wid  = tid >> 5;
    const int lane = tid & 31;
    const int g    = lane >> 2;
    const int t4   = lane & 3;
    const int wm   = wid & 3;
    const int wn   = wid >> 2;
    const int bm   = byi * 128;
    const int bn   = bxi * 128;

    float c[2][8][4];
#pragma unroll
    for (int mt = 0; mt < 2; mt++)
#pragma unroll
        for (int nt = 0; nt < 8; nt++)
#pragma unroll
            for (int i = 0; i < 4; i++) c[mt][nt][i] = 0.0f;

    const int ar = tid >> 3, aq = tid & 7;     // A coords (row step 32)
    const int br = tid >> 5, bq = tid & 31;    // B coords (row step 8)

#define LOAD_TILE(stage, kbase)                                                  \
    do {                                                                         \
        _Pragma("unroll")                                                        \
        for (int i = 0; i < 4; i++) {                                            \
            int r = ar + i * 32;                                                 \
            CP16(smem_u32(&AS(stage, r, aq * 4)),                                \
                 A + (size_t)(bm + r) * lda + (kbase) + aq * 4);                 \
        }                                                                        \
        _Pragma("unroll")                                                        \
        for (int i = 0; i < 4; i++) {                                            \
            int r = br + i * 8;                                                  \
            CP16(smem_u32(&BS(stage, r, bq * 4)),                                \
                 W + (size_t)((kbase) + r) * N + bn + bq * 4);                   \
        }                                                                        \
        CP_COMMIT();                                                             \
    } while (0)

    LOAD_TILE(0, 0);
    CP_WAIT0();
    __syncthreads();

    int buf = 0;
    for (int k0 = 0; k0 < K; k0 += 32) {
        const bool has_next = (k0 + 32) < K;
        if (has_next) LOAD_TILE(buf ^ 1, k0 + 32);

#pragma unroll
        for (int kb = 0; kb < 4; kb++) {
            const int kk = kb * 8;
            unsigned a[2][4], b[8][2];
#pragma unroll
            for (int mt = 0; mt < 2; mt++) {
                int r = wm * 32 + mt * 16 + g;
                a[mt][0] = __float_as_uint(AS(buf, r,     kk + t4));
                a[mt][1] = __float_as_uint(AS(buf, r + 8, kk + t4));
                a[mt][2] = __float_as_uint(AS(buf, r,     kk + t4 + 4));
                a[mt][3] = __float_as_uint(AS(buf, r + 8, kk + t4 + 4));
            }
#pragma unroll
            for (int nt = 0; nt < 8; nt++) {
                int cb = wn * 64 + nt * 8;
                b[nt][0] = __float_as_uint(BS(buf, kk + t4,     cb + g));
                b[nt][1] = __float_as_uint(BS(buf, kk + t4 + 4, cb + g));
            }
#pragma unroll
            for (int mt = 0; mt < 2; mt++)
#pragma unroll
                for (int nt = 0; nt < 8; nt++)
                    mma8(c[mt][nt], a[mt], b[nt]);
        }

        if (has_next) CP_WAIT0();
        __syncthreads();
        buf ^= 1;
    }

    // epilogue
#pragma unroll
    for (int mt = 0; mt < 2; mt++) {
        int r0 = bm + wm * 32 + mt * 16 + g;
        int r1 = r0 + 8;
#pragma unroll
        for (int nt = 0; nt < 8; nt++) {
            int col = bn + wn * 64 + nt * 8 + t4 * 2;
            float v00 = c[mt][nt][0];
            float v01 = c[mt][nt][1];
            float v10 = c[mt][nt][2];
            float v11 = c[mt][nt][3];
            if (MODE != 3) {
                float bb0 = bias[col], bb1 = bias[col + 1];
                v00 += bb0; v01 += bb1; v10 += bb0; v11 += bb1;
            }
            if (MODE == 1) {
                v00 = gelu_exact(v00); v01 = gelu_exact(v01);
                v10 = gelu_exact(v10); v11 = gelu_exact(v11);
            }
            if (MODE == 2) {
                float2 r0v = *(const float2*)(Res + (size_t)r0 * N + col);
                float2 r1v = *(const float2*)(Res + (size_t)r1 * N + col);
                v00 += r0v.x; v01 += r0v.y; v10 += r1v.x; v11 += r1v.y;
            }
            float2 o0 = {v00, v01}, o1 = {v10, v11};
            *(float2*)(C + (size_t)r0 * N + col) = o0;
            *(float2*)(C + (size_t)r1 * N + col) = o1;
        }
    }
#undef AS
#undef BS
#undef LOAD_TILE
}

template <int MODE>
__global__ void __launch_bounds__(256)
gemm_tc(const float* __restrict__ A, const float* __restrict__ W,
        const float* __restrict__ bias, const float* __restrict__ Res,
        float* __restrict__ C, int M, int N, int K) {
    gemm_body<MODE>(A, W, bias, Res, C, M, N, K, K, blockIdx.x, blockIdx.y);
}

// Split-K=3 partial GEMM: grid.z selects K-third and output partial buffer.
// 576 blocks -> 1.95 occ-2 waves fully packed (384 blocks left a 88-block tail wave).
__global__ void __launch_bounds__(256)
gemm_part3(const float* __restrict__ A, const float* __restrict__ W,
           float* __restrict__ C0, float* __restrict__ C1, float* __restrict__ C2,
           int M, int N, int Kfull) {
    const int z  = blockIdx.z;
    const int kt = Kfull / 3;
    const float* Az = A + (size_t)z * kt;          // column offset into A
    const float* Wz = W + (size_t)z * kt * N;      // row offset into W
    float* C = (z == 0) ? C0 : (z == 1) ? C1 : C2;
    gemm_body<3>(Az, Wz, nullptr, nullptr, C, M, N, kt, Kfull,
                 blockIdx.x, blockIdx.y);
}

// Fused QKV: grid.x = 18 (6 col-blocks per projection).
__global__ void __launch_bounds__(256)
gemm_qkv(const float* __restrict__ A,
         const float* __restrict__ Wq, const float* __restrict__ Wk, const float* __restrict__ Wv,
         const float* __restrict__ bq, const float* __restrict__ bk, const float* __restrict__ bv,
         float* __restrict__ Oq, float* __restrict__ Ok, float* __restrict__ Ov,
         int M, int K) {
    int sel = blockIdx.x / 6;
    int bx  = blockIdx.x - sel * 6;
    const float* W    = (sel == 0) ? Wq : (sel == 1) ? Wk : Wv;
    const float* bias = (sel == 0) ? bq : (sel == 1) ? bk : bv;
    float*       C    = (sel == 0) ? Oq : (sel == 1) ? Ok : Ov;
    gemm_body<0>(A, W, bias, nullptr, C, M, D_MODEL, K, K, bx, blockIdx.y);
}

// ---------------------------------------------------------------------------
// Flash attention (R10): BQ=128, BKV=64, double-buffered cp.async pipeline.
// ---------------------------------------------------------------------------
#define BQ  128
#define BKV 64

__global__ void __launch_bounds__(256, 3)
attn_tc3(const float* __restrict__ Q, const float* __restrict__ K,
         const float* __restrict__ V, const int* __restrict__ mask,
         float* __restrict__ O) {
    __shared__ __align__(16) float Ks[2][64][68];
    __shared__ __align__(16) float Vs[2][64][68];
    __shared__ __align__(16) int   Ms[2][64];

    const int bh   = blockIdx.y;
    const int b    = bh / N_HEADS;
    const int h    = bh % N_HEADS;
    const int q0   = blockIdx.x * BQ;
    const int tid  = threadIdx.x;
    const int wid  = tid >> 5;
    const int lane = tid & 31;
    const int g    = lane >> 2;
    const int t4   = lane & 3;

    const float* Qb = Q + (size_t)b * S_LEN * D_MODEL + h * D_K;
    const float* Kb = K + (size_t)b * S_LEN * D_MODEL + h * D_K;
    const float* Vb = V + (size_t)b * S_LEN * D_MODEL + h * D_K;
    const int*   mb = mask + b * S_LEN;

    // ---- stage Q (128 x 64) through Ks[0]/Vs[0], then into registers ----
#pragma unroll
    for (int i = 0; i < 8; i++) {
        int f = tid + i * 256;
        int r = f >> 4, dq = f & 15;
        float4 v = *(const float4*)(Qb + (size_t)(q0 + r) * D_MODEL + dq * 4);
        if (r < 64) *(float4*)&Ks[0][r][dq * 4]      = v;
        else        *(float4*)&Vs[0][r - 64][dq * 4] = v;
    }
    __syncthreads();

    unsigned qf[8][4];
    {
        int r0 = wid * 16 + g;
        int r1 = r0 + 8;
        const float* row0 = (r0 < 64) ? &Ks[0][r0][0] : &Vs[0][r0 - 64][0];
        const float* row1 = (r1 < 64) ? &Ks[0][r1][0] : &Vs[0][r1 - 64][0];
#pragma unroll
        for (int kb = 0; kb < 8; kb++) {
            qf[kb][0] = __float_as_uint(row0[kb * 8 + t4]);
            qf[kb][1] = __float_as_uint(row1[kb * 8 + t4]);
            qf[kb][2] = __float_as_uint(row0[kb * 8 + t4 + 4]);
            qf[kb][3] = __float_as_uint(row1[kb * 8 + t4 + 4]);
        }
    }
    __syncthreads();   // all qf read before tile 0 overwrites Ks[0]/Vs[0]

    // full tile copy: 1024 16B-chunks each for K and V -> 4+4 CP16 per thread
#define LOAD_KV(stage, kbase)                                                    \
    do {                                                                         \
        _Pragma("unroll")                                                        \
        for (int i = 0; i < 4; i++) {                                            \
            int f = tid + i * 256;                                               \
            int r = f >> 4, dq = f & 15;                                         \
            CP16(smem_u32(&Ks[stage][r][dq * 4]),                                \
                 Kb + (size_t)((kbase) + r) * D_MODEL + dq * 4);                 \
            CP16(smem_u32(&Vs[stage][r][dq * 4]),                                \
                 Vb + (size_t)((kbase) + r) * D_MODEL + dq * 4);                 \
        }                                                                        \
        if (tid < 16)                                                            \
            CP16(smem_u32(&Ms[stage][tid * 4]), mb + (kbase) + tid * 4);         \
        CP_COMMIT();                                                             \
    } while (0)

    float o[8][4];
#pragma unroll
    for (int nt = 0; nt < 8; nt++)
#pragma unroll
        for (int i = 0; i < 4; i++) o[nt][i] = 0.0f;
    float m0 = -1e30f, m1 = -1e30f, l0 = 0.0f, l1 = 0.0f;

    const int  srcA = (lane & 28) | (t4 >> 1);
    const int  srcB = srcA + 2;
    const bool odd  = (t4 & 1) != 0;

    LOAD_KV(0, 0);

    int buf = 0;
    for (int k0 = 0; k0 < S_LEN; k0 += BKV) {
        CP_WAIT0();          // tile k0 resident
        __syncthreads();     // visible to all; prior compute done with buf^1
        if (k0 + BKV < S_LEN) LOAD_KV(buf ^ 1, k0 + BKV);

        // S = Q @ K^T  (16 q-rows x 64 kv per warp)
        float s[8][4];
#pragma unroll
        for (int nb = 0; nb < 8; nb++) {
            s[nb][0] = 0.0f; s[nb][1] = 0.0f; s[nb][2] = 0.0f; s[nb][3] = 0.0f;
        }
#pragma unroll
        for (int kb = 0; kb < 8; kb++) {
#pragma unroll
            for (int nb = 0; nb < 8; nb++) {
                unsigned bfr[2] = {
                    __float_as_uint(Ks[buf][nb * 8 + g][kb * 8 + t4]),
                    __float_as_uint(Ks[buf][nb * 8 + g][kb * 8 + t4 + 4]) };
                mma8(s[nb], qf[kb], bfr);
            }
        }

        // mask + scale + row max
        float mx0 = -1e30f, mx1 = -1e30f;
#pragma unroll
        for (int nb = 0; nb < 8; nb++) {
            int2 mm = *(const int2*)&Ms[buf][nb * 8 + 2 * t4];
            float bx = mm.x ? 0.0f : -1e9f;
            float by = mm.y ? 0.0f : -1e9f;
            s[nb][0] = s[nb][0] * 0.125f + bx;
            s[nb][1] = s[nb][1] * 0.125f + by;
            s[nb][2] = s[nb][2] * 0.125f + bx;
            s[nb][3] = s[nb][3] * 0.125f + by;
            mx0 = fmaxf(mx0, fmaxf(s[nb][0], s[nb][1]));
            mx1 = fmaxf(mx1, fmaxf(s[nb][2], s[nb][3]));
        }
        mx0 = fmaxf(mx0, __shfl_xor_sync(0xffffffffu, mx0, 1));
        mx0 = fmaxf(mx0, __shfl_xor_sync(0xffffffffu, mx0, 2));
        mx1 = fmaxf(mx1, __shfl_xor_sync(0xffffffffu, mx1, 1));
        mx1 = fmaxf(mx1, __shfl_xor_sync(0xffffffffu, mx1, 2));

        float mn0 = fmaxf(m0, mx0), mn1 = fmaxf(m1, mx1);
        float a0 = __expf(m0 - mn0), a1 = __expf(m1 - mn1);
        m0 = mn0; m1 = mn1;

        float ps0 = 0.0f, ps1 = 0.0f;
#pragma unroll
        for (int nb = 0; nb < 8; nb++) {
            float p0 = __expf(s[nb][0] - mn0); ps0 += p0;
            float p1 = __expf(s[nb][1] - mn0); ps0 += p1;
            float p2 = __expf(s[nb][2] - mn1); ps1 += p2;
            float p3 = __expf(s[nb][3] - mn1); ps1 += p3;
            s[nb][0] = p0; s[nb][1] = p1; s[nb][2] = p2; s[nb][3] = p3;
        }
        ps0 += __shfl_xor_sync(0xffffffffu, ps0, 1);
        ps0 += __shfl_xor_sync(0xffffffffu, ps0, 2);
        ps1 += __shfl_xor_sync(0xffffffffu, ps1, 1);
        ps1 += __shfl_xor_sync(0xffffffffu, ps1, 2);
        l0 = l0 * a0 + ps0;
        l1 = l1 * a1 + ps1;

        // rescale O
#pragma unroll
        for (int nt = 0; nt < 8; nt++) {
            o[nt][0] *= a0; o[nt][1] *= a0;
            o[nt][2] *= a1; o[nt][3] *= a1;
        }

        // O += P @ V   (P fragments via warp shuffles from score fragments)
#pragma unroll
        for (int kb2 = 0; kb2 < 8; kb2++) {
            unsigned c0 = __float_as_uint(s[kb2][0]);
            unsigned c1 = __float_as_uint(s[kb2][1]);
            unsigned c2 = __float_as_uint(s[kb2][2]);
            unsigned c3 = __float_as_uint(s[kb2][3]);
            unsigned e0 = __shfl_sync(0xffffffffu, c0, srcA);
            unsigned e1 = __shfl_sync(0xffffffffu, c1, srcA);
            unsigned e2 = __shfl_sync(0xffffffffu, c2, srcA);
            unsigned e3 = __shfl_sync(0xffffffffu, c3, srcA);
            unsigned f0 = __shfl_sync(0xffffffffu, c0, srcB);
            unsigned f1 = __shfl_sync(0xffffffffu, c1, srcB);
            unsigned f2 = __shfl_sync(0xffffffffu, c2, srcB);
            unsigned f3 = __shfl_sync(0xffffffffu, c3, srcB);
            unsigned af[4];
            af[0] = odd ? e1 : e0;
            af[1] = odd ? e3 : e2;
            af[2] = odd ? f1 : f0;
            af[3] = odd ? f3 : f2;
#pragma unroll
            for (int nt = 0; nt < 8; nt++) {
                unsigned bfr[2] = {
                    __float_as_uint(Vs[buf][kb2 * 8 + t4][nt * 8 + g]),
                    __float_as_uint(Vs[buf][kb2 * 8 + t4 + 4][nt * 8 + g]) };
                mma8(o[nt], af, bfr);
            }
        }
        buf ^= 1;
    }

    // finalize
    float il0 = 1.0f / l0, il1 = 1.0f / l1;
    int r0 = q0 + wid * 16 + g;
    size_t g0 = (size_t)(b * S_LEN + r0) * D_MODEL + h * D_K;
    size_t g1 = (size_t)(b * S_LEN + r0 + 8) * D_MODEL + h * D_K;
#pragma unroll
    for (int nt = 0; nt < 8; nt++) {
        float2 o0 = {o[nt][0] * il0, o[nt][1] * il0};
        float2 o1 = {o[nt][2] * il1, o[nt][3] * il1};
        *(float2*)(O + g0 + nt * 8 + 2 * t4) = o0;
        *(float2*)(O + g1 + nt * 8 + 2 * t4) = o1;
    }
#undef LOAD_KV
}

// ---------------------------------------------------------------------------
// Fused split-K=3 reduce + residual + bias + LayerNorm.
// out = LN(res + p0 + p1 + p2 + bias). One block per row, 192 threads x float4.
// ---------------------------------------------------------------------------
__global__ void __launch_bounds__(192)
ln_fuse_kernel(const float* __restrict__ p0, const float* __restrict__ p1,
               const float* __restrict__ p2,
               const float* __restrict__ bias, const float* __restrict__ res,
               const float* __restrict__ gamma, const float* __restrict__ beta,
               float* __restrict__ out) {
    const int row = blockIdx.x;
    const int tid = threadIdx.x;
    const size_t base = (size_t)row * D_MODEL + tid * 4;

    float4 a0 = *(const float4*)(p0 + base);
    float4 a1 = *(const float4*)(p1 + base);
    float4 a2 = *(const float4*)(p2 + base);
    float4 rr = *(const float4*)(res + base);
    float4 bb = *(const float4*)(bias + tid * 4);
    float4 v;
    v.x = a0.x + a1.x + a2.x + rr.x + bb.x;
    v.y = a0.y + a1.y + a2.y + rr.y + bb.y;
    v.z = a0.z + a1.z + a2.z + rr.z + bb.z;
    v.w = a0.w + a1.w + a2.w + rr.w + bb.w;

    float s  = v.x + v.y + v.z + v.w;
    float sq = v.x * v.x + v.y * v.y + v.z * v.z + v.w * v.w;
#pragma unroll
    for (int off = 16; off > 0; off >>= 1) {
        s  += __shfl_xor_sync(0xffffffffu, s,  off);
        sq += __shfl_xor_sync(0xffffffffu, sq, off);
    }
    __shared__ float ss[6], ssq[6];
    int wid = tid >> 5, lane = tid & 31;
    if (lane == 0) { ss[wid] = s; ssq[wid] = sq; }
    __syncthreads();
    s = 0.0f; sq = 0.0f;
#pragma unroll
    for (int w = 0; w < 6; w++) { s += ss[w]; sq += ssq[w]; }

    const float inv_n = 1.0f / (float)D_MODEL;
    float mean = s * inv_n;
    float var  = sq * inv_n - mean * mean;
    float rstd = rsqrtf(var + 1e-5f);

    float4 gm = *(const float4*)(gamma + tid * 4);
    float4 bt = *(const float4*)(beta + tid * 4);
    float4 o;
    o.x = (v.x - mean) * rstd * gm.x + bt.x;
    o.y = (v.y - mean) * rstd * gm.y + bt.y;
    o.z = (v.z - mean) * rstd * gm.z + bt.z;
    o.w = (v.w - mean) * rstd * gm.w + bt.w;
    *(float4*)(out + base) = o;
}

// ---------------------------------------------------------------------------
// Launch
// ---------------------------------------------------------------------------
extern "C" void kernel_launch(void* const* d_in, const int* in_sizes, int n_in,
                              void* d_out, int out_size) {
    const float* x    = (const float*)d_in[0];
    const int*   mask = (const int*)  d_in[1];
    const float* wq = (const float*)d_in[2];
    const float* bq = (const float*)d_in[3];
    const float* wk = (const float*)d_in[4];
    const float* bk = (const float*)d_in[5];
    const float* wv = (const float*)d_in[6];
    const float* bv = (const float*)d_in[7];
    const float* wo = (const float*)d_in[8];
    const float* bo = (const float*)d_in[9];
    const float* w1 = (const float*)d_in[10];
    const float* b1 = (const float*)d_in[11];
    const float* w2 = (const float*)d_in[12];
    const float* b2 = (const float*)d_in[13];
    const float* g1 = (const float*)d_in[14];
    const float* be1= (const float*)d_in[15];
    const float* g2 = (const float*)d_in[16];
    const float* be2= (const float*)d_in[17];
    float* out = (float*)d_out;

    void* sptr = nullptr;
    cudaGetSymbolAddress(&sptr, g_scratch);
    float* S = (float*)sptr;
    float* q_b = S + OFF_Q;
    float* k_b = S + OFF_K;
    float* v_b = S + OFF_V;
    float* ctx = S + OFF_CTX;
    float* p0  = S + OFF_P0;
    float* x1  = S + OFF_X1;
    float* p1  = S + OFF_P1;
    float* p2  = S + OFF_Q;       // q region is dead after attention
    float* ff  = S + OFF_FF;

    cudaFuncSetAttribute(gemm_qkv,   cudaFuncAttributeMaxDynamicSharedMemorySize, GEMM_SMEM_BYTES);
    cudaFuncSetAttribute(gemm_part3, cudaFuncAttributeMaxDynamicSharedMemorySize, GEMM_SMEM_BYTES);
    cudaFuncSetAttribute(gemm_tc<1>, cudaFuncAttributeMaxDynamicSharedMemorySize, GEMM_SMEM_BYTES);

    dim3 blk(256);
    dim3 grid_qkv(18, M_ROWS / 128);                  // 576 blocks
    dim3 grid_dm3(D_MODEL / 128, M_ROWS / 128, 3);    // 576 blocks (split-K=3)
    dim3 grid_ff(D_FF / 128,   M_ROWS / 128);         // 768 blocks

    gemm_qkv<<<grid_qkv, blk, GEMM_SMEM_BYTES>>>(x, wq, wk, wv, bq, bk, bv,
                                                 q_b, k_b, v_b, M_ROWS, D_MODEL);

    dim3 agrid(S_LEN / BQ, B_SZ * N_HEADS);           // 384 blocks
    attn_tc3<<<agrid, blk>>>(q_b, k_b, v_b, mask, ctx);

    // wo-projection, split-K=3 -> partials; LN1 fuses reduce+bias+residual
    gemm_part3<<<grid_dm3, blk, GEMM_SMEM_BYTES>>>(ctx, wo, p0, p1, p2,
                                                   M_ROWS, D_MODEL, D_MODEL);
    ln_fuse_kernel<<<M_ROWS, 192>>>(p0, p1, p2, bo, x, g1, be1, x1);

    // FFN1 (gelu epilogue)
    gemm_tc<1><<<grid_ff, blk, GEMM_SMEM_BYTES>>>(x1, w1, b1, nullptr, ff,
                                                  M_ROWS, D_FF, D_MODEL);

    // FFN2, split-K=3 -> partials; LN2 fuses reduce+bias+residual
    gemm_part3<<<grid_dm3, blk, GEMM_SMEM_BYTES>>>(ff, w2, p0, p1, p2,
                                                   M_ROWS, D_MODEL, D_FF);
    ln_fuse_kernel<<<M_ROWS, 192>>>(p0, p1, p2, b2, x1, g2, be2, out);
}